// round 1
// baseline (speedup 1.0000x reference)
#include <cuda_runtime.h>
#include <cstdint>

// Problem constants (fixed shapes from reference)
#define BATCH 4096
#define DIM   512
#define GRID  128
#define NCELL (GRID*GRID)   // 16384
#define THR_REL 0.95f
#define LR_MAX 0.2f
#define LR_MIN 0.05f
#define CTX_MAX 2
#define CTX_MIN 0

// ---------------- device scratch (static, allocation-free) ----------------
__device__ float               g_wnorm[NCELL];
__device__ unsigned long long  g_min[BATCH];      // packed (orderable distbits<<32 | cell)
__device__ unsigned long long  g_cls[BATCH];      // class-constrained packed
__device__ float               g_S0[NCELL * DIM]; // per-(transposed)BMU sum of x
__device__ float               g_cnt[NCELL];
__device__ float               g_sum;             // sum of min_dists
__device__ float               g_lr;
__device__ int                 g_ctx;

// ---------------- schedule (epoch -> lr, ctx) ----------------
__global__ void schedule_kernel(const int* __restrict__ epoch,
                                const int* __restrict__ max_epochs) {
    int e = epoch[0], me = max_epochs[0];
    float progress = (me > 0) ? (float)(me - e) / (float)me : 0.0f;
    progress = fminf(fmaxf(progress, 0.0f), 1.0f);
    float p2 = progress * progress;
    float p4 = p2 * p2;
    g_ctx = CTX_MIN + (int)(p4 * (float)(CTX_MAX - CTX_MIN));
    g_lr  = LR_MIN + progress * (LR_MAX - LR_MIN);
}

// ---------------- w_norm: one warp per cell ----------------
__global__ void wnorm_kernel(const float* __restrict__ W) {
    int warp = (blockIdx.x * blockDim.x + threadIdx.x) >> 5;
    int lane = threadIdx.x & 31;
    if (warp >= NCELL) return;
    const float4* row = (const float4*)(W + (size_t)warp * DIM);
    float s = 0.0f;
    #pragma unroll
    for (int i = 0; i < 4; i++) {
        float4 v = row[lane + 32 * i];
        s += v.x*v.x + v.y*v.y + v.z*v.z + v.w*v.w;
    }
    #pragma unroll
    for (int o = 16; o; o >>= 1) s += __shfl_xor_sync(0xFFFFFFFFu, s, o);
    if (lane == 0) g_wnorm[warp] = s;
}

// ---------------- distance GEMM + fused dual argmin ----------------
// C = -2 * X W^T (+w_norm), track per-row packed min (plain and class-masked).
#define BM 128
#define BN 128
#define BK 16
#define TM 8
#define TN 8

__device__ __forceinline__ unsigned float_to_ordered(float f) {
    unsigned u = __float_as_uint(f);
    return (u & 0x80000000u) ? ~u : (u ^ 0x80000000u);
}

__global__ __launch_bounds__(256, 2)
void dist_argmin_kernel(const float* __restrict__ X,
                        const float* __restrict__ W,
                        const int*   __restrict__ labels,
                        const int*   __restrict__ cell_labels) {
    __shared__ float As[BK][BM];
    __shared__ float Bs[BK][BN];

    const int tid = threadIdx.x;
    const int tx = tid & 15;
    const int ty = tid >> 4;
    const int rowBase = blockIdx.y * BM;
    const int colBase = blockIdx.x * BN;

    float acc[TM][TN];
    #pragma unroll
    for (int i = 0; i < TM; i++)
        #pragma unroll
        for (int j = 0; j < TN; j++) acc[i][j] = 0.0f;

    for (int k0 = 0; k0 < DIM; k0 += BK) {
        #pragma unroll
        for (int it = 0; it < 2; it++) {
            int idx = tid + it * 256;     // 0..511 float4 slots
            int r   = idx >> 2;           // 0..127
            int c4  = idx & 3;            // float4 within the 16-wide k slab
            float4 va = *(const float4*)&X[(size_t)(rowBase + r) * DIM + k0 + c4 * 4];
            As[c4*4+0][r] = va.x; As[c4*4+1][r] = va.y;
            As[c4*4+2][r] = va.z; As[c4*4+3][r] = va.w;
            float4 vb = *(const float4*)&W[(size_t)(colBase + r) * DIM + k0 + c4 * 4];
            Bs[c4*4+0][r] = vb.x; Bs[c4*4+1][r] = vb.y;
            Bs[c4*4+2][r] = vb.z; Bs[c4*4+3][r] = vb.w;
        }
        __syncthreads();
        #pragma unroll
        for (int k = 0; k < BK; k++) {
            float4 a0 = *(const float4*)&As[k][ty * TM];
            float4 a1 = *(const float4*)&As[k][ty * TM + 4];
            float4 b0 = *(const float4*)&Bs[k][tx * TN];
            float4 b1 = *(const float4*)&Bs[k][tx * TN + 4];
            float a[TM] = {a0.x,a0.y,a0.z,a0.w,a1.x,a1.y,a1.z,a1.w};
            float b[TN] = {b0.x,b0.y,b0.z,b0.w,b1.x,b1.y,b1.z,b1.w};
            #pragma unroll
            for (int i = 0; i < TM; i++)
                #pragma unroll
                for (int j = 0; j < TN; j++)
                    acc[i][j] += a[i] * b[j];
        }
        __syncthreads();
    }

    // epilogue: s = w_norm - 2*dot ; per-row packed min over block's 128 cols
    float wn[TN]; int clab[TN];
    #pragma unroll
    for (int j = 0; j < TN; j++) {
        int col = colBase + tx * TN + j;
        wn[j]   = g_wnorm[col];
        clab[j] = cell_labels[col];
    }
    #pragma unroll
    for (int i = 0; i < TM; i++) {
        int row = rowBase + ty * TM + i;
        int lab = labels[row];
        unsigned long long pmin = ~0ull, pcls = ~0ull;
        #pragma unroll
        for (int j = 0; j < TN; j++) {
            unsigned col = (unsigned)(colBase + tx * TN + j);
            float s = fmaf(-2.0f, acc[i][j], wn[j]);
            unsigned long long p =
                ((unsigned long long)float_to_ordered(s) << 32) | col;
            pmin = (p < pmin) ? p : pmin;
            if (clab[j] == lab) pcls = (p < pcls) ? p : pcls;
        }
        #pragma unroll
        for (int o = 8; o; o >>= 1) {
            unsigned long long q;
            q = __shfl_xor_sync(0xFFFFFFFFu, pmin, o, 16);
            pmin = (q < pmin) ? q : pmin;
            q = __shfl_xor_sync(0xFFFFFFFFu, pcls, o, 16);
            pcls = (q < pcls) ? q : pcls;
        }
        if (tx == 0) {
            atomicMin(&g_min[row], pmin);
            atomicMin(&g_cls[row], pcls);
        }
    }
}

// ---------------- per-sample: som_errors, min_dist sum, BMU scatter ----------------
__global__ void persample_kernel(const float* __restrict__ X,
                                 const float* __restrict__ W,
                                 const float* __restrict__ cell_rel,
                                 float* __restrict__ out_err) {
    const int i = blockIdx.x;
    const int t = threadIdx.x;   // 128 threads, 4 floats each
    float4 x = *(const float4*)&X[(size_t)i * DIM + t * 4];

    // block-reduce x_norm
    float s = x.x*x.x + x.y*x.y + x.z*x.z + x.w*x.w;
    #pragma unroll
    for (int o = 16; o; o >>= 1) s += __shfl_xor_sync(0xFFFFFFFFu, s, o);
    __shared__ float red[4];
    if ((t & 31) == 0) red[t >> 5] = s;
    __syncthreads();
    float xn = red[0] + red[1] + red[2] + red[3];

    unsigned long long pm = g_min[i];
    unsigned long long pc = g_cls[i];
    unsigned bmu = (unsigned)pm;
    unsigned ub  = (unsigned)(pm >> 32);
    ub = (ub & 0x80000000u) ? (ub ^ 0x80000000u) : ~ub;   // inverse ordered map
    float smin = __uint_as_float(ub);
    if (t == 0) atomicAdd(&g_sum, fmaxf(xn + smin, 0.0f));

    unsigned cls = (unsigned)pc;
    if (cls >= (unsigned)NCELL) cls = 0;   // all-masked guard (jnp argmin of inf -> 0)

    float rel = cell_rel[cls] / 100.0f;
    float fac = (rel >= THR_REL) ? 0.01f * rel : 0.0f;
    float4 w = *(const float4*)&W[(size_t)cls * DIM + t * 4];
    float4 e;
    e.x = fac * (w.x - x.x);
    e.y = fac * (w.y - x.y);
    e.z = fac * (w.z - x.z);
    e.w = fac * (w.w - x.w);
    *(float4*)&out_err[(size_t)i * DIM + t * 4] = e;

    // transposed-center scatter (reference x/y convention)
    int bx = (int)(bmu / GRID), by = (int)(bmu % GRID);
    int center = by * GRID + bx;
    float* dst = &g_S0[(size_t)center * DIM + t * 4];
    atomicAdd(dst + 0, x.x);
    atomicAdd(dst + 1, x.y);
    atomicAdd(dst + 2, x.z);
    atomicAdd(dst + 3, x.w);
    if (t == 0) atomicAdd(&g_cnt[center], 1.0f);
}

// ---------------- stencil conv + SOM update ----------------
__global__ void update_kernel(const float* __restrict__ som,
                              float* __restrict__ out_som) {
    const int cell = blockIdx.x;
    const int a = cell >> 7, c = cell & 127;
    const int t = threadIdx.x;   // 128 threads * float4 = 512
    const int ctx = g_ctx;
    const float lr = g_lr;
    const bool flag = (g_sum / (float)BATCH) > 1e-4f;

    float denom = 0.0f;
    float4 num = make_float4(0.f, 0.f, 0.f, 0.f);
    for (int dy = -ctx; dy <= ctx; dy++) {
        int aa = a + dy;
        if (aa < 0 || aa >= GRID) continue;
        for (int dx = -ctx; dx <= ctx; dx++) {
            int cc = c + dx;
            if (cc < 0 || cc >= GRID) continue;
            int ch = max(abs(dy), abs(dx));
            float w = ldexpf(lr, -ch);     // lr / 2^cheb, exact
            int nb = aa * GRID + cc;
            denom += w * g_cnt[nb];
            float4 sv = *(const float4*)&g_S0[(size_t)nb * DIM + t * 4];
            num.x += w * sv.x; num.y += w * sv.y;
            num.z += w * sv.z; num.w += w * sv.w;
        }
    }
    float4 sm = *(const float4*)&som[(size_t)cell * DIM + t * 4];
    float4 o;
    if (flag) {
        o.x = sm.x + num.x - sm.x * denom;
        o.y = sm.y + num.y - sm.y * denom;
        o.z = sm.z + num.z - sm.z * denom;
        o.w = sm.w + num.w - sm.w * denom;
    } else {
        o = sm;
    }
    *(float4*)&out_som[(size_t)cell * DIM + t * 4] = o;
}

// ---------------- launch ----------------
extern "C" void kernel_launch(void* const* d_in, const int* in_sizes, int n_in,
                              void* d_out, int out_size) {
    const float* X          = (const float*)d_in[0];
    const int*   labels     = (const int*)  d_in[1];
    const float* som        = (const float*)d_in[2];
    const int*   cell_lab   = (const int*)  d_in[3];
    const float* cell_rel   = (const float*)d_in[4];
    const int*   epoch      = (const int*)  d_in[5];
    const int*   max_epochs = (const int*)  d_in[6];
    (void)in_sizes; (void)n_in; (void)out_size;

    float* out_err = (float*)d_out;
    float* out_som = (float*)d_out + (size_t)BATCH * DIM;

    void *pS0, *pCnt, *pMin, *pCls, *pSum;
    cudaGetSymbolAddress(&pS0,  g_S0);
    cudaGetSymbolAddress(&pCnt, g_cnt);
    cudaGetSymbolAddress(&pMin, g_min);
    cudaGetSymbolAddress(&pCls, g_cls);
    cudaGetSymbolAddress(&pSum, g_sum);

    cudaMemsetAsync(pS0,  0,    sizeof(float) * (size_t)NCELL * DIM);
    cudaMemsetAsync(pCnt, 0,    sizeof(float) * NCELL);
    cudaMemsetAsync(pMin, 0xFF, sizeof(unsigned long long) * BATCH);
    cudaMemsetAsync(pCls, 0xFF, sizeof(unsigned long long) * BATCH);
    cudaMemsetAsync(pSum, 0,    sizeof(float));

    schedule_kernel<<<1, 1>>>(epoch, max_epochs);
    wnorm_kernel<<<NCELL / 8, 256>>>(som);
    dist_argmin_kernel<<<dim3(NCELL / BN, BATCH / BM), 256>>>(X, som, labels, cell_lab);
    persample_kernel<<<BATCH, 128>>>(X, som, cell_rel, out_err);
    update_kernel<<<NCELL, 128>>>(som, out_som);
}

// round 4
// speedup vs baseline: 2.0337x; 2.0337x over previous
#include <cuda_runtime.h>
#include <cuda_bf16.h>
#include <cstdint>

#define BATCH 4096
#define DIM   512
#define GRID  128
#define NCELL (GRID*GRID)   // 16384
#define THR_REL 0.95f
#define LR_MAX 0.2f
#define LR_MIN 0.05f
#define CTX_MAX 2
#define CTX_MIN 0

// GEMM tiling: CTA 128x128, 8 warps (2x4), warp 64x32, k-slab 64
#define KC 64
#define NS (DIM/KC)          // 8 stages
#define APITCH 144           // bytes per smem row (64 bf16 = 128B data + 16B pad)
#define ARR (128*APITCH)     // 18432 bytes per smem array
#define STG (4*ARR)          // Ah, Al, Bh, Bl
#define HDR 1536
#define SMEMT (HDR + 2*STG)  // 148992
#define NPART 512            // (NCELL/128 col tiles) * 4 warp-col groups

typedef unsigned long long u64;

// ---------------- device scratch ----------------
__device__ float          g_wnorm[NCELL];
__device__ u64            g_min[BATCH];
__device__ u64            g_cls[BATCH];
__device__ float          g_S0[NCELL * DIM];
__device__ float          g_cnt[NCELL];
__device__ float          g_sum;
__device__ float          g_lr;
__device__ int            g_ctx;
__device__ __nv_bfloat16  g_xh[BATCH*DIM];
__device__ __nv_bfloat16  g_xl[BATCH*DIM];
__device__ __nv_bfloat16  g_wh[NCELL*DIM];
__device__ __nv_bfloat16  g_wl[NCELL*DIM];
__device__ u64            g_part[(size_t)NPART * BATCH * 4];

// ---------------- PTX helpers (baseline ISA only) ----------------
__device__ __forceinline__ uint32_t smem_to_u32(const void* p) {
    uint32_t a;
    asm("{ .reg .u64 t; cvta.to.shared.u64 t, %1; cvt.u32.u64 %0, t; }" : "=r"(a) : "l"(p));
    return a;
}
#define CP_ASYNC16(d, s) \
    asm volatile("cp.async.cg.shared.global [%0], [%1], 16;" :: "r"(d), "l"(s) : "memory")
#define CP_COMMIT() asm volatile("cp.async.commit_group;" ::: "memory")
#define CP_WAIT(n)  asm volatile("cp.async.wait_group %0;" :: "n"(n) : "memory")

#define LDSM_X4(r, a) \
    asm volatile("ldmatrix.sync.aligned.m8n8.x4.shared.b16 {%0,%1,%2,%3}, [%4];" \
        : "=r"((r)[0]), "=r"((r)[1]), "=r"((r)[2]), "=r"((r)[3]) : "r"(a))
#define LDSM_X2(r, a) \
    asm volatile("ldmatrix.sync.aligned.m8n8.x2.shared.b16 {%0,%1}, [%2];" \
        : "=r"((r)[0]), "=r"((r)[1]) : "r"(a))
#define MMA_BF16(dd, aa, bb) \
    asm volatile("mma.sync.aligned.m16n8k16.row.col.f32.bf16.bf16.f32 " \
        "{%0,%1,%2,%3}, {%4,%5,%6,%7}, {%8,%9}, {%0,%1,%2,%3};" \
        : "+f"((dd)[0]), "+f"((dd)[1]), "+f"((dd)[2]), "+f"((dd)[3]) \
        : "r"((aa)[0]), "r"((aa)[1]), "r"((aa)[2]), "r"((aa)[3]), \
          "r"((bb)[0]), "r"((bb)[1]))

__device__ __forceinline__ unsigned float_to_ordered(float f) {
    unsigned u = __float_as_uint(f);
    return (u & 0x80000000u) ? ~u : (u ^ 0x80000000u);
}
__device__ __forceinline__ void top2_ins(u64& m1, u64& m2, u64 v) {
    if (v < m1) { m2 = m1; m1 = v; } else if (v < m2) { m2 = v; }
}

// ---------------- schedule ----------------
__global__ void schedule_kernel(const int* __restrict__ epoch,
                                const int* __restrict__ max_epochs) {
    int e = epoch[0], me = max_epochs[0];
    float progress = (me > 0) ? (float)(me - e) / (float)me : 0.0f;
    progress = fminf(fmaxf(progress, 0.0f), 1.0f);
    float p2 = progress * progress;
    g_ctx = CTX_MIN + (int)(p2 * p2 * (float)(CTX_MAX - CTX_MIN));
    g_lr  = LR_MIN + progress * (LR_MAX - LR_MIN);
}

// ---------------- bf16 hi/lo split ----------------
__global__ void split_bf16_kernel(const float* __restrict__ src,
                                  __nv_bfloat16* __restrict__ hi,
                                  __nv_bfloat16* __restrict__ lo, int n4) {
    int stride = gridDim.x * blockDim.x;
    for (int i = blockIdx.x * blockDim.x + threadIdx.x; i < n4; i += stride) {
        float4 v = ((const float4*)src)[i];
        union { __nv_bfloat16 b[4]; uint2 u; } H, L;
        H.b[0] = __float2bfloat16_rn(v.x);
        H.b[1] = __float2bfloat16_rn(v.y);
        H.b[2] = __float2bfloat16_rn(v.z);
        H.b[3] = __float2bfloat16_rn(v.w);
        L.b[0] = __float2bfloat16_rn(v.x - __bfloat162float(H.b[0]));
        L.b[1] = __float2bfloat16_rn(v.y - __bfloat162float(H.b[1]));
        L.b[2] = __float2bfloat16_rn(v.z - __bfloat162float(H.b[2]));
        L.b[3] = __float2bfloat16_rn(v.w - __bfloat162float(H.b[3]));
        ((uint2*)hi)[i] = H.u;
        ((uint2*)lo)[i] = L.u;
    }
}

// ---------------- w_norm ----------------
__global__ void wnorm_kernel(const float* __restrict__ W) {
    int warp = (blockIdx.x * blockDim.x + threadIdx.x) >> 5;
    int lane = threadIdx.x & 31;
    if (warp >= NCELL) return;
    const float4* row = (const float4*)(W + (size_t)warp * DIM);
    float s = 0.0f;
    #pragma unroll
    for (int i = 0; i < 4; i++) {
        float4 v = row[lane + 32 * i];
        s += v.x*v.x + v.y*v.y + v.z*v.z + v.w*v.w;
    }
    #pragma unroll
    for (int o = 16; o; o >>= 1) s += __shfl_xor_sync(0xFFFFFFFFu, s, o);
    if (lane == 0) g_wnorm[warp] = s;
}

// ---------------- bf16 mma.sync GEMM + fused top-2 argmin ----------------
__global__ __launch_bounds__(256, 1)
void mma_argmin_kernel(const int* __restrict__ labels,
                       const int* __restrict__ cell_labels) {
    extern __shared__ char sm[];
    const uint32_t sbase = smem_to_u32(sm);
    const int tid = threadIdx.x;
    const int lane = tid & 31;
    const int wid = tid >> 5;
    const int rowBase = blockIdx.y * 128;
    const int colBase = blockIdx.x * 128;

    float* wn_s = (float*)sm;
    int*   cl_s = (int*)(sm + 512);
    int*   rl_s = (int*)(sm + 1024);
    if (tid < 128) {
        wn_s[tid] = g_wnorm[colBase + tid];
        cl_s[tid] = cell_labels[colBase + tid];
        rl_s[tid] = labels[rowBase + tid];
    }

    const int m0  = (wid >> 2) * 64;
    const int n0v = (wid & 3) * 32;

    float d[4][4][4];
    #pragma unroll
    for (int mi = 0; mi < 4; mi++)
        #pragma unroll
        for (int nj = 0; nj < 4; nj++)
            #pragma unroll
            for (int e = 0; e < 4; e++) d[mi][nj][e] = 0.0f;

    // lane-address components for ldmatrix
    const uint32_t aR = (uint32_t)(lane & 15);
    const uint32_t aK = (uint32_t)((lane >> 4) * 8);
    const uint32_t bR = (uint32_t)(lane & 7);
    const uint32_t bK = (uint32_t)(((lane >> 3) & 1) * 8);

    // stage loader via cp.async (16B chunks)
    auto load_stage = [&](int s) {
        const int k0 = s * KC;
        const uint32_t st = (uint32_t)HDR + (uint32_t)(s & 1) * STG;
        #pragma unroll
        for (int i = 0; i < 4; i++) {
            int slot = tid + i * 256;            // 0..1023
            int r = slot >> 3, q = slot & 7;
            uint32_t doff = sbase + st + (uint32_t)(r * APITCH + q * 16);
            const __nv_bfloat16* sxh = &g_xh[(size_t)(rowBase + r) * DIM + k0 + q * 8];
            const __nv_bfloat16* sxl = &g_xl[(size_t)(rowBase + r) * DIM + k0 + q * 8];
            const __nv_bfloat16* swh = &g_wh[(size_t)(colBase + r) * DIM + k0 + q * 8];
            const __nv_bfloat16* swl = &g_wl[(size_t)(colBase + r) * DIM + k0 + q * 8];
            CP_ASYNC16(doff,           sxh);
            CP_ASYNC16(doff + ARR,     sxl);
            CP_ASYNC16(doff + 2*ARR,   swh);
            CP_ASYNC16(doff + 3*ARR,   swl);
        }
    };

    load_stage(0); CP_COMMIT();

    for (int s = 0; s < NS; s++) {
        if (s + 1 < NS) { load_stage(s + 1); CP_COMMIT(); CP_WAIT(1); }
        else            { CP_WAIT(0); }
        __syncthreads();
        const uint32_t st = sbase + (uint32_t)HDR + (uint32_t)(s & 1) * STG;
        #pragma unroll
        for (int ks = 0; ks < KC / 16; ks++) {
            uint32_t ah[4][4], al[4][4], bh[4][2], bl[4][2];
            #pragma unroll
            for (int mi = 0; mi < 4; mi++) {
                uint32_t ad = st + (uint32_t)((m0 + mi * 16 + aR) * APITCH) +
                              (uint32_t)((ks * 16 + aK) * 2);
                LDSM_X4(ah[mi], ad);
                LDSM_X4(al[mi], ad + ARR);
            }
            #pragma unroll
            for (int nj = 0; nj < 4; nj++) {
                uint32_t bd = st + 2*ARR + (uint32_t)((n0v + nj * 8 + bR) * APITCH) +
                              (uint32_t)((ks * 16 + bK) * 2);
                LDSM_X2(bh[nj], bd);
                LDSM_X2(bl[nj], bd + ARR);
            }
            #pragma unroll
            for (int mi = 0; mi < 4; mi++)
                #pragma unroll
                for (int nj = 0; nj < 4; nj++) {
                    MMA_BF16(d[mi][nj], ah[mi], bh[nj]);
                    MMA_BF16(d[mi][nj], ah[mi], bl[nj]);
                    MMA_BF16(d[mi][nj], al[mi], bh[nj]);
                }
        }
        __syncthreads();
    }

    // ---- fused epilogue: per-row top-2 (plain + class-masked) ----
    const int g  = lane >> 2;
    const int t4 = lane & 3;
    #pragma unroll
    for (int mi = 0; mi < 4; mi++) {
        const int lr0 = m0 + mi * 16 + g;
        const int lr1 = lr0 + 8;
        const int lab0 = rl_s[lr0];
        const int lab1 = rl_s[lr1];
        u64 m1a = ~0ull, m2a = ~0ull, c1a = ~0ull, c2a = ~0ull;
        u64 m1b = ~0ull, m2b = ~0ull, c1b = ~0ull, c2b = ~0ull;
        #pragma unroll
        for (int nj = 0; nj < 4; nj++) {
            #pragma unroll
            for (int e = 0; e < 2; e++) {
                int lc = n0v + nj * 8 + t4 * 2 + e;
                float wn = wn_s[lc];
                int   cl = cl_s[lc];
                unsigned col = (unsigned)(colBase + lc);
                float s0 = fmaf(-2.0f, d[mi][nj][e], wn);
                u64 p0 = ((u64)float_to_ordered(s0) << 32) | col;
                top2_ins(m1a, m2a, p0);
                if (cl == lab0) top2_ins(c1a, c2a, p0);
                float s1 = fmaf(-2.0f, d[mi][nj][2 + e], wn);
                u64 p1 = ((u64)float_to_ordered(s1) << 32) | col;
                top2_ins(m1b, m2b, p1);
                if (cl == lab1) top2_ins(c1b, c2b, p1);
            }
        }
        #pragma unroll
        for (int o = 1; o <= 2; o <<= 1) {
            u64 q1, q2;
            q1 = __shfl_xor_sync(0xFFFFFFFFu, m1a, o); q2 = __shfl_xor_sync(0xFFFFFFFFu, m2a, o);
            top2_ins(m1a, m2a, q1); top2_ins(m1a, m2a, q2);
            q1 = __shfl_xor_sync(0xFFFFFFFFu, c1a, o); q2 = __shfl_xor_sync(0xFFFFFFFFu, c2a, o);
            top2_ins(c1a, c2a, q1); top2_ins(c1a, c2a, q2);
            q1 = __shfl_xor_sync(0xFFFFFFFFu, m1b, o); q2 = __shfl_xor_sync(0xFFFFFFFFu, m2b, o);
            top2_ins(m1b, m2b, q1); top2_ins(m1b, m2b, q2);
            q1 = __shfl_xor_sync(0xFFFFFFFFu, c1b, o); q2 = __shfl_xor_sync(0xFFFFFFFFu, c2b, o);
            top2_ins(c1b, c2b, q1); top2_ins(c1b, c2b, q2);
        }
        if (t4 == 0) {
            const size_t tileIdx = (size_t)(blockIdx.x * 4 + (wid & 3));
            size_t pb = (tileIdx * BATCH + (size_t)(rowBase + lr0)) * 4;
            g_part[pb+0] = m1a; g_part[pb+1] = m2a; g_part[pb+2] = c1a; g_part[pb+3] = c2a;
            pb = (tileIdx * BATCH + (size_t)(rowBase + lr1)) * 4;
            g_part[pb+0] = m1b; g_part[pb+1] = m2b; g_part[pb+2] = c1b; g_part[pb+3] = c2b;
        }
    }
}

// ---------------- merge partials + exact fp32 rescore ----------------
__device__ __forceinline__ float warp_dot(const float* __restrict__ x,
                                          const float* __restrict__ w, int lane) {
    const float4* xv = (const float4*)x + lane * 4;
    const float4* wv = (const float4*)w + lane * 4;
    float acc = 0.0f;
    #pragma unroll
    for (int q = 0; q < 4; q++) {
        float4 a = xv[q], b = wv[q];
        acc = fmaf(a.x, b.x, acc); acc = fmaf(a.y, b.y, acc);
        acc = fmaf(a.z, b.z, acc); acc = fmaf(a.w, b.w, acc);
    }
    #pragma unroll
    for (int o = 16; o; o >>= 1) acc += __shfl_xor_sync(0xFFFFFFFFu, acc, o);
    return acc;
}

__global__ void reduce_rescore_kernel(const float* __restrict__ X,
                                      const float* __restrict__ W) {
    const int lane = threadIdx.x & 31;
    const int row = blockIdx.x * 8 + (threadIdx.x >> 5);

    u64 m1 = ~0ull, m2 = ~0ull, c1 = ~0ull, c2 = ~0ull;
    #pragma unroll
    for (int t = 0; t < NPART / 32; t++) {
        int tile = lane + t * 32;
        const ulonglong2* p = (const ulonglong2*)&g_part[((size_t)tile * BATCH + row) * 4];
        ulonglong2 a = p[0], b = p[1];
        top2_ins(m1, m2, a.x); top2_ins(m1, m2, a.y);
        top2_ins(c1, c2, b.x); top2_ins(c1, c2, b.y);
    }
    #pragma unroll
    for (int o = 16; o; o >>= 1) {
        u64 q1 = __shfl_xor_sync(0xFFFFFFFFu, m1, o);
        u64 q2 = __shfl_xor_sync(0xFFFFFFFFu, m2, o);
        top2_ins(m1, m2, q1); top2_ins(m1, m2, q2);
        q1 = __shfl_xor_sync(0xFFFFFFFFu, c1, o);
        q2 = __shfl_xor_sync(0xFFFFFFFFu, c2, o);
        top2_ins(c1, c2, q1); top2_ins(c1, c2, q2);
    }

    const float* xr = X + (size_t)row * DIM;

    unsigned i1 = (unsigned)m1, i2 = (unsigned)m2;
    float s1 = g_wnorm[i1] - 2.0f * warp_dot(xr, W + (size_t)i1 * DIM, lane);
    float s2 = g_wnorm[i2] - 2.0f * warp_dot(xr, W + (size_t)i2 * DIM, lane);
    unsigned best = i1; float sb = s1;
    if (s2 < sb || (s2 == sb && i2 < best)) { best = i2; sb = s2; }
    if (lane == 0)
        g_min[row] = ((u64)float_to_ordered(sb) << 32) | best;

    u64 outc = ~0ull;
    if (c1 != ~0ull) {
        unsigned j1 = (unsigned)c1;
        float t1 = g_wnorm[j1] - 2.0f * warp_dot(xr, W + (size_t)j1 * DIM, lane);
        unsigned bc = j1; float tb = t1;
        if (c2 != ~0ull) {
            unsigned j2 = (unsigned)c2;
            float t2 = g_wnorm[j2] - 2.0f * warp_dot(xr, W + (size_t)j2 * DIM, lane);
            if (t2 < tb || (t2 == tb && j2 < bc)) { bc = j2; tb = t2; }
        }
        outc = ((u64)float_to_ordered(tb) << 32) | bc;
    }
    if (lane == 0) g_cls[row] = outc;
}

// ---------------- per-sample: som_errors, min_dist sum, BMU scatter ----------------
__global__ void persample_kernel(const float* __restrict__ X,
                                 const float* __restrict__ W,
                                 const float* __restrict__ cell_rel,
                                 float* __restrict__ out_err) {
    const int i = blockIdx.x;
    const int t = threadIdx.x;
    float4 x = *(const float4*)&X[(size_t)i * DIM + t * 4];

    float s = x.x*x.x + x.y*x.y + x.z*x.z + x.w*x.w;
    #pragma unroll
    for (int o = 16; o; o >>= 1) s += __shfl_xor_sync(0xFFFFFFFFu, s, o);
    __shared__ float red[4];
    if ((t & 31) == 0) red[t >> 5] = s;
    __syncthreads();
    float xn = red[0] + red[1] + red[2] + red[3];

    u64 pm = g_min[i];
    u64 pc = g_cls[i];
    unsigned bmu = (unsigned)pm;
    unsigned ub  = (unsigned)(pm >> 32);
    ub = (ub & 0x80000000u) ? (ub ^ 0x80000000u) : ~ub;
    float smin = __uint_as_float(ub);
    if (t == 0) atomicAdd(&g_sum, fmaxf(xn + smin, 0.0f));

    unsigned cls = (unsigned)pc;
    if (cls >= (unsigned)NCELL) cls = 0;

    float rel = cell_rel[cls] / 100.0f;
    float fac = (rel >= THR_REL) ? 0.01f * rel : 0.0f;
    float4 w = *(const float4*)&W[(size_t)cls * DIM + t * 4];
    float4 e;
    e.x = fac * (w.x - x.x);
    e.y = fac * (w.y - x.y);
    e.z = fac * (w.z - x.z);
    e.w = fac * (w.w - x.w);
    *(float4*)&out_err[(size_t)i * DIM + t * 4] = e;

    int bx = (int)(bmu / GRID), by = (int)(bmu % GRID);
    int center = by * GRID + bx;
    float* dst = &g_S0[(size_t)center * DIM + t * 4];
    atomicAdd(dst + 0, x.x);
    atomicAdd(dst + 1, x.y);
    atomicAdd(dst + 2, x.z);
    atomicAdd(dst + 3, x.w);
    if (t == 0) atomicAdd(&g_cnt[center], 1.0f);
}

// ---------------- stencil conv + SOM update ----------------
__global__ void update_kernel(const float* __restrict__ som,
                              float* __restrict__ out_som) {
    const int cell = blockIdx.x;
    const int a = cell >> 7, c = cell & 127;
    const int t = threadIdx.x;
    const int ctx = g_ctx;
    const float lr = g_lr;
    const bool flag = (g_sum / (float)BATCH) > 1e-4f;

    float denom = 0.0f;
    float4 num = make_float4(0.f, 0.f, 0.f, 0.f);
    for (int dy = -ctx; dy <= ctx; dy++) {
        int aa = a + dy;
        if (aa < 0 || aa >= GRID) continue;
        for (int dx = -ctx; dx <= ctx; dx++) {
            int cc = c + dx;
            if (cc < 0 || cc >= GRID) continue;
            int ch = max(abs(dy), abs(dx));
            float w = ldexpf(lr, -ch);
            int nb = aa * GRID + cc;
            denom += w * g_cnt[nb];
            float4 sv = *(const float4*)&g_S0[(size_t)nb * DIM + t * 4];
            num.x += w * sv.x; num.y += w * sv.y;
            num.z += w * sv.z; num.w += w * sv.w;
        }
    }
    float4 smv = *(const float4*)&som[(size_t)cell * DIM + t * 4];
    float4 o;
    if (flag) {
        o.x = smv.x + num.x - smv.x * denom;
        o.y = smv.y + num.y - smv.y * denom;
        o.z = smv.z + num.z - smv.z * denom;
        o.w = smv.w + num.w - smv.w * denom;
    } else {
        o = smv;
    }
    *(float4*)&out_som[(size_t)cell * DIM + t * 4] = o;
}

// ---------------- launch ----------------
extern "C" void kernel_launch(void* const* d_in, const int* in_sizes, int n_in,
                              void* d_out, int out_size) {
    const float* X          = (const float*)d_in[0];
    const int*   labels     = (const int*)  d_in[1];
    const float* som        = (const float*)d_in[2];
    const int*   cell_lab   = (const int*)  d_in[3];
    const float* cell_rel   = (const float*)d_in[4];
    const int*   epoch      = (const int*)  d_in[5];
    const int*   max_epochs = (const int*)  d_in[6];
    (void)in_sizes; (void)n_in; (void)out_size;

    float* out_err = (float*)d_out;
    float* out_som = (float*)d_out + (size_t)BATCH * DIM;

    cudaFuncSetAttribute(mma_argmin_kernel,
                         cudaFuncAttributeMaxDynamicSharedMemorySize, SMEMT);

    void *pS0, *pCnt, *pSum;
    cudaGetSymbolAddress(&pS0,  g_S0);
    cudaGetSymbolAddress(&pCnt, g_cnt);
    cudaGetSymbolAddress(&pSum, g_sum);
    cudaMemsetAsync(pS0,  0, sizeof(float) * (size_t)NCELL * DIM);
    cudaMemsetAsync(pCnt, 0, sizeof(float) * NCELL);
    cudaMemsetAsync(pSum, 0, sizeof(float));

    void *pxh, *pxl, *pwh, *pwl;
    cudaGetSymbolAddress(&pxh, g_xh); cudaGetSymbolAddress(&pxl, g_xl);
    cudaGetSymbolAddress(&pwh, g_wh); cudaGetSymbolAddress(&pwl, g_wl);

    schedule_kernel<<<1, 1>>>(epoch, max_epochs);
    split_bf16_kernel<<<1024, 256>>>(X,   (__nv_bfloat16*)pxh, (__nv_bfloat16*)pxl,
                                     BATCH * DIM / 4);
    split_bf16_kernel<<<2048, 256>>>(som, (__nv_bfloat16*)pwh, (__nv_bfloat16*)pwl,
                                     NCELL * DIM / 4);
    wnorm_kernel<<<NCELL / 8, 256>>>(som);
    mma_argmin_kernel<<<dim3(NCELL / 128, BATCH / 128), 256, SMEMT>>>(labels, cell_lab);
    reduce_rescore_kernel<<<BATCH / 8, 256>>>(X, som);
    persample_kernel<<<BATCH, 128>>>(X, som, cell_rel, out_err);
    update_kernel<<<NCELL, 128>>>(som, out_som);
}

// round 5
// speedup vs baseline: 2.6445x; 1.3004x over previous
#include <cuda_runtime.h>
#include <cuda_bf16.h>
#include <cstdint>

#define BATCH 4096
#define DIM   512
#define GRID  128
#define NCELL (GRID*GRID)   // 16384
#define THR_REL 0.95f
#define LR_MAX 0.2f
#define LR_MIN 0.05f
#define CTX_MAX 2
#define CTX_MIN 0

// GEMM tiling: CTA 128x128, 8 warps (2x4), warp 64x32, k-slab 64, 3-stage pipe
#define KC 64
#define NS (DIM/KC)          // 8 stages
#define APITCH 144           // bytes per smem row (64 bf16 = 128B data + 16B pad)
#define ARR (128*APITCH)     // 18432 bytes per smem array
#define STG (3*ARR)          // Ah, Bh, Bl = 55296
#define HDR 1536
#define SMEMT (HDR + 3*STG)  // 167424
#define NPART 512            // (NCELL/128 col tiles) * 4 warp-col groups

typedef unsigned long long u64;

// ---------------- device scratch ----------------
__device__ float          g_wnorm[NCELL];
__device__ u64            g_min[BATCH];
__device__ u64            g_cls[BATCH];
__device__ float          g_S0[NCELL * DIM];
__device__ float          g_cnt[NCELL];
__device__ float          g_sum;
__device__ float          g_lr;
__device__ int            g_ctx;
__device__ __nv_bfloat16  g_xh[BATCH*DIM];
__device__ __nv_bfloat16  g_wh[NCELL*DIM];
__device__ __nv_bfloat16  g_wl[NCELL*DIM];
__device__ u64            g_part[(size_t)NPART * BATCH * 4];

// ---------------- PTX helpers (baseline ISA only) ----------------
__device__ __forceinline__ uint32_t smem_to_u32(const void* p) {
    uint32_t a;
    asm("{ .reg .u64 t; cvta.to.shared.u64 t, %1; cvt.u32.u64 %0, t; }" : "=r"(a) : "l"(p));
    return a;
}
#define CP_ASYNC16(d, s) \
    asm volatile("cp.async.cg.shared.global [%0], [%1], 16;" :: "r"(d), "l"(s) : "memory")
#define CP_COMMIT() asm volatile("cp.async.commit_group;" ::: "memory")
#define CP_WAIT(n)  asm volatile("cp.async.wait_group %0;" :: "n"(n) : "memory")

#define LDSM_X4(r, a) \
    asm volatile("ldmatrix.sync.aligned.m8n8.x4.shared.b16 {%0,%1,%2,%3}, [%4];" \
        : "=r"((r)[0]), "=r"((r)[1]), "=r"((r)[2]), "=r"((r)[3]) : "r"(a))
#define LDSM_X2(r, a) \
    asm volatile("ldmatrix.sync.aligned.m8n8.x2.shared.b16 {%0,%1}, [%2];" \
        : "=r"((r)[0]), "=r"((r)[1]) : "r"(a))
#define MMA_BF16(dd, aa, bb) \
    asm volatile("mma.sync.aligned.m16n8k16.row.col.f32.bf16.bf16.f32 " \
        "{%0,%1,%2,%3}, {%4,%5,%6,%7}, {%8,%9}, {%0,%1,%2,%3};" \
        : "+f"((dd)[0]), "+f"((dd)[1]), "+f"((dd)[2]), "+f"((dd)[3]) \
        : "r"((aa)[0]), "r"((aa)[1]), "r"((aa)[2]), "r"((aa)[3]), \
          "r"((bb)[0]), "r"((bb)[1]))

__device__ __forceinline__ unsigned float_to_ordered(float f) {
    unsigned u = __float_as_uint(f);
    return (u & 0x80000000u) ? ~u : (u ^ 0x80000000u);
}
__device__ __forceinline__ void top2_ins(u64& m1, u64& m2, u64 v) {
    if (v < m1) { m2 = m1; m1 = v; } else if (v < m2) { m2 = v; }
}

// ---------------- schedule ----------------
__global__ void schedule_kernel(const int* __restrict__ epoch,
                                const int* __restrict__ max_epochs) {
    int e = epoch[0], me = max_epochs[0];
    float progress = (me > 0) ? (float)(me - e) / (float)me : 0.0f;
    progress = fminf(fmaxf(progress, 0.0f), 1.0f);
    float p2 = progress * progress;
    g_ctx = CTX_MIN + (int)(p2 * p2 * (float)(CTX_MAX - CTX_MIN));
    g_lr  = LR_MIN + progress * (LR_MAX - LR_MIN);
}

// ---------------- bf16 splits ----------------
__global__ void split_hi_kernel(const float* __restrict__ src,
                                __nv_bfloat16* __restrict__ hi, int n4) {
    int stride = gridDim.x * blockDim.x;
    for (int i = blockIdx.x * blockDim.x + threadIdx.x; i < n4; i += stride) {
        float4 v = ((const float4*)src)[i];
        union { __nv_bfloat16 b[4]; uint2 u; } H;
        H.b[0] = __float2bfloat16_rn(v.x);
        H.b[1] = __float2bfloat16_rn(v.y);
        H.b[2] = __float2bfloat16_rn(v.z);
        H.b[3] = __float2bfloat16_rn(v.w);
        ((uint2*)hi)[i] = H.u;
    }
}

__global__ void split_bf16_kernel(const float* __restrict__ src,
                                  __nv_bfloat16* __restrict__ hi,
                                  __nv_bfloat16* __restrict__ lo, int n4) {
    int stride = gridDim.x * blockDim.x;
    for (int i = blockIdx.x * blockDim.x + threadIdx.x; i < n4; i += stride) {
        float4 v = ((const float4*)src)[i];
        union { __nv_bfloat16 b[4]; uint2 u; } H, L;
        H.b[0] = __float2bfloat16_rn(v.x);
        H.b[1] = __float2bfloat16_rn(v.y);
        H.b[2] = __float2bfloat16_rn(v.z);
        H.b[3] = __float2bfloat16_rn(v.w);
        L.b[0] = __float2bfloat16_rn(v.x - __bfloat162float(H.b[0]));
        L.b[1] = __float2bfloat16_rn(v.y - __bfloat162float(H.b[1]));
        L.b[2] = __float2bfloat16_rn(v.z - __bfloat162float(H.b[2]));
        L.b[3] = __float2bfloat16_rn(v.w - __bfloat162float(H.b[3]));
        ((uint2*)hi)[i] = H.u;
        ((uint2*)lo)[i] = L.u;
    }
}

// ---------------- w_norm ----------------
__global__ void wnorm_kernel(const float* __restrict__ W) {
    int warp = (blockIdx.x * blockDim.x + threadIdx.x) >> 5;
    int lane = threadIdx.x & 31;
    if (warp >= NCELL) return;
    const float4* row = (const float4*)(W + (size_t)warp * DIM);
    float s = 0.0f;
    #pragma unroll
    for (int i = 0; i < 4; i++) {
        float4 v = row[lane + 32 * i];
        s += v.x*v.x + v.y*v.y + v.z*v.z + v.w*v.w;
    }
    #pragma unroll
    for (int o = 16; o; o >>= 1) s += __shfl_xor_sync(0xFFFFFFFFu, s, o);
    if (lane == 0) g_wnorm[warp] = s;
}

// ---------------- bf16 mma.sync GEMM (2-term) + fused top-2 argmin ----------------
__global__ __launch_bounds__(256, 1)
void mma_argmin_kernel(const int* __restrict__ labels,
                       const int* __restrict__ cell_labels) {
    extern __shared__ char sm[];
    const uint32_t sbase = smem_to_u32(sm);
    const int tid = threadIdx.x;
    const int lane = tid & 31;
    const int wid = tid >> 5;
    const int rowBase = blockIdx.y * 128;
    const int colBase = blockIdx.x * 128;

    float* wn_s = (float*)sm;
    int*   cl_s = (int*)(sm + 512);
    int*   rl_s = (int*)(sm + 1024);
    if (tid < 128) {
        wn_s[tid] = g_wnorm[colBase + tid];
        cl_s[tid] = cell_labels[colBase + tid];
        rl_s[tid] = labels[rowBase + tid];
    }

    const int m0  = (wid >> 2) * 64;
    const int n0v = (wid & 3) * 32;

    float d[4][4][4];
    #pragma unroll
    for (int mi = 0; mi < 4; mi++)
        #pragma unroll
        for (int nj = 0; nj < 4; nj++)
            #pragma unroll
            for (int e = 0; e < 4; e++) d[mi][nj][e] = 0.0f;

    // lane-address components for ldmatrix
    const uint32_t aR = (uint32_t)(lane & 15);
    const uint32_t aK = (uint32_t)((lane >> 4) * 8);
    const uint32_t bR = (uint32_t)(lane & 7);
    const uint32_t bK = (uint32_t)(((lane >> 3) & 1) * 8);

    // stage loader via cp.async: Ah, Bh, Bl (12 x 16B per thread)
    auto load_stage = [&](int s) {
        const int k0 = s * KC;
        const uint32_t st = (uint32_t)HDR + (uint32_t)(s % 3) * STG;
        #pragma unroll
        for (int i = 0; i < 4; i++) {
            int slot = tid + i * 256;            // 0..1023
            int r = slot >> 3, q = slot & 7;
            uint32_t doff = sbase + st + (uint32_t)(r * APITCH + q * 16);
            CP_ASYNC16(doff,         &g_xh[(size_t)(rowBase + r) * DIM + k0 + q * 8]);
            CP_ASYNC16(doff + ARR,   &g_wh[(size_t)(colBase + r) * DIM + k0 + q * 8]);
            CP_ASYNC16(doff + 2*ARR, &g_wl[(size_t)(colBase + r) * DIM + k0 + q * 8]);
        }
    };

    load_stage(0); CP_COMMIT();
    load_stage(1); CP_COMMIT();

    for (int s = 0; s < NS; s++) {
        CP_WAIT(1);
        __syncthreads();
        const uint32_t st = sbase + (uint32_t)HDR + (uint32_t)(s % 3) * STG;
        #pragma unroll
        for (int ks = 0; ks < KC / 16; ks++) {
            uint32_t ah[4][4], bh[4][2], bl[4][2];
            #pragma unroll
            for (int mi = 0; mi < 4; mi++) {
                uint32_t ad = st + (uint32_t)((m0 + mi * 16 + aR) * APITCH) +
                              (uint32_t)((ks * 16 + aK) * 2);
                LDSM_X4(ah[mi], ad);
            }
            #pragma unroll
            for (int nj = 0; nj < 4; nj++) {
                uint32_t bd = st + ARR + (uint32_t)((n0v + nj * 8 + bR) * APITCH) +
                              (uint32_t)((ks * 16 + bK) * 2);
                LDSM_X2(bh[nj], bd);
                LDSM_X2(bl[nj], bd + ARR);
            }
            #pragma unroll
            for (int mi = 0; mi < 4; mi++)
                #pragma unroll
                for (int nj = 0; nj < 4; nj++) {
                    MMA_BF16(d[mi][nj], ah[mi], bh[nj]);
                    MMA_BF16(d[mi][nj], ah[mi], bl[nj]);
                }
        }
        if (s + 2 < NS) { load_stage(s + 2); CP_COMMIT(); }
    }

    // ---- fused epilogue: per-row top-2 (plain + class-masked) ----
    const int g  = lane >> 2;
    const int t4 = lane & 3;
    #pragma unroll
    for (int mi = 0; mi < 4; mi++) {
        const int lr0 = m0 + mi * 16 + g;
        const int lr1 = lr0 + 8;
        const int lab0 = rl_s[lr0];
        const int lab1 = rl_s[lr1];
        u64 m1a = ~0ull, m2a = ~0ull, c1a = ~0ull, c2a = ~0ull;
        u64 m1b = ~0ull, m2b = ~0ull, c1b = ~0ull, c2b = ~0ull;
        #pragma unroll
        for (int nj = 0; nj < 4; nj++) {
            #pragma unroll
            for (int e = 0; e < 2; e++) {
                int lc = n0v + nj * 8 + t4 * 2 + e;
                float wn = wn_s[lc];
                int   cl = cl_s[lc];
                unsigned col = (unsigned)(colBase + lc);
                float s0 = fmaf(-2.0f, d[mi][nj][e], wn);
                u64 p0 = ((u64)float_to_ordered(s0) << 32) | col;
                top2_ins(m1a, m2a, p0);
                if (cl == lab0) top2_ins(c1a, c2a, p0);
                float s1 = fmaf(-2.0f, d[mi][nj][2 + e], wn);
                u64 p1 = ((u64)float_to_ordered(s1) << 32) | col;
                top2_ins(m1b, m2b, p1);
                if (cl == lab1) top2_ins(c1b, c2b, p1);
            }
        }
        #pragma unroll
        for (int o = 1; o <= 2; o <<= 1) {
            u64 q1, q2;
            q1 = __shfl_xor_sync(0xFFFFFFFFu, m1a, o); q2 = __shfl_xor_sync(0xFFFFFFFFu, m2a, o);
            top2_ins(m1a, m2a, q1); top2_ins(m1a, m2a, q2);
            q1 = __shfl_xor_sync(0xFFFFFFFFu, c1a, o); q2 = __shfl_xor_sync(0xFFFFFFFFu, c2a, o);
            top2_ins(c1a, c2a, q1); top2_ins(c1a, c2a, q2);
            q1 = __shfl_xor_sync(0xFFFFFFFFu, m1b, o); q2 = __shfl_xor_sync(0xFFFFFFFFu, m2b, o);
            top2_ins(m1b, m2b, q1); top2_ins(m1b, m2b, q2);
            q1 = __shfl_xor_sync(0xFFFFFFFFu, c1b, o); q2 = __shfl_xor_sync(0xFFFFFFFFu, c2b, o);
            top2_ins(c1b, c2b, q1); top2_ins(c1b, c2b, q2);
        }
        if (t4 == 0) {
            const size_t tileIdx = (size_t)(blockIdx.x * 4 + (wid & 3));
            size_t pb = (tileIdx * BATCH + (size_t)(rowBase + lr0)) * 4;
            g_part[pb+0] = m1a; g_part[pb+1] = m2a; g_part[pb+2] = c1a; g_part[pb+3] = c2a;
            pb = (tileIdx * BATCH + (size_t)(rowBase + lr1)) * 4;
            g_part[pb+0] = m1b; g_part[pb+1] = m2b; g_part[pb+2] = c1b; g_part[pb+3] = c2b;
        }
    }
}

// ---------------- merge partials + exact fp32 rescore ----------------
__device__ __forceinline__ float warp_dot(const float* __restrict__ x,
                                          const float* __restrict__ w, int lane) {
    const float4* xv = (const float4*)x + lane * 4;
    const float4* wv = (const float4*)w + lane * 4;
    float acc = 0.0f;
    #pragma unroll
    for (int q = 0; q < 4; q++) {
        float4 a = xv[q], b = wv[q];
        acc = fmaf(a.x, b.x, acc); acc = fmaf(a.y, b.y, acc);
        acc = fmaf(a.z, b.z, acc); acc = fmaf(a.w, b.w, acc);
    }
    #pragma unroll
    for (int o = 16; o; o >>= 1) acc += __shfl_xor_sync(0xFFFFFFFFu, acc, o);
    return acc;
}

__global__ void reduce_rescore_kernel(const float* __restrict__ X,
                                      const float* __restrict__ W) {
    const int lane = threadIdx.x & 31;
    const int row = blockIdx.x * 8 + (threadIdx.x >> 5);

    u64 m1 = ~0ull, m2 = ~0ull, c1 = ~0ull, c2 = ~0ull;
    #pragma unroll
    for (int t = 0; t < NPART / 32; t++) {
        int tile = lane + t * 32;
        const ulonglong2* p = (const ulonglong2*)&g_part[((size_t)tile * BATCH + row) * 4];
        ulonglong2 a = p[0], b = p[1];
        top2_ins(m1, m2, a.x); top2_ins(m1, m2, a.y);
        top2_ins(c1, c2, b.x); top2_ins(c1, c2, b.y);
    }
    #pragma unroll
    for (int o = 16; o; o >>= 1) {
        u64 q1 = __shfl_xor_sync(0xFFFFFFFFu, m1, o);
        u64 q2 = __shfl_xor_sync(0xFFFFFFFFu, m2, o);
        top2_ins(m1, m2, q1); top2_ins(m1, m2, q2);
        q1 = __shfl_xor_sync(0xFFFFFFFFu, c1, o);
        q2 = __shfl_xor_sync(0xFFFFFFFFu, c2, o);
        top2_ins(c1, c2, q1); top2_ins(c1, c2, q2);
    }

    const float* xr = X + (size_t)row * DIM;

    unsigned i1 = (unsigned)m1, i2 = (unsigned)m2;
    float s1 = g_wnorm[i1] - 2.0f * warp_dot(xr, W + (size_t)i1 * DIM, lane);
    float s2 = g_wnorm[i2] - 2.0f * warp_dot(xr, W + (size_t)i2 * DIM, lane);
    unsigned best = i1; float sb = s1;
    if (s2 < sb || (s2 == sb && i2 < best)) { best = i2; sb = s2; }
    if (lane == 0)
        g_min[row] = ((u64)float_to_ordered(sb) << 32) | best;

    u64 outc = ~0ull;
    if (c1 != ~0ull) {
        unsigned j1 = (unsigned)c1;
        float t1 = g_wnorm[j1] - 2.0f * warp_dot(xr, W + (size_t)j1 * DIM, lane);
        unsigned bc = j1; float tb = t1;
        if (c2 != ~0ull) {
            unsigned j2 = (unsigned)c2;
            float t2 = g_wnorm[j2] - 2.0f * warp_dot(xr, W + (size_t)j2 * DIM, lane);
            if (t2 < tb || (t2 == tb && j2 < bc)) { bc = j2; tb = t2; }
        }
        outc = ((u64)float_to_ordered(tb) << 32) | bc;
    }
    if (lane == 0) g_cls[row] = outc;
}

// ---------------- per-sample: som_errors, min_dist sum, BMU scatter ----------------
__global__ void persample_kernel(const float* __restrict__ X,
                                 const float* __restrict__ W,
                                 const float* __restrict__ cell_rel,
                                 float* __restrict__ out_err) {
    const int i = blockIdx.x;
    const int t = threadIdx.x;
    float4 x = *(const float4*)&X[(size_t)i * DIM + t * 4];

    float s = x.x*x.x + x.y*x.y + x.z*x.z + x.w*x.w;
    #pragma unroll
    for (int o = 16; o; o >>= 1) s += __shfl_xor_sync(0xFFFFFFFFu, s, o);
    __shared__ float red[4];
    if ((t & 31) == 0) red[t >> 5] = s;
    __syncthreads();
    float xn = red[0] + red[1] + red[2] + red[3];

    u64 pm = g_min[i];
    u64 pc = g_cls[i];
    unsigned bmu = (unsigned)pm;
    unsigned ub  = (unsigned)(pm >> 32);
    ub = (ub & 0x80000000u) ? (ub ^ 0x80000000u) : ~ub;
    float smin = __uint_as_float(ub);
    if (t == 0) atomicAdd(&g_sum, fmaxf(xn + smin, 0.0f));

    unsigned cls = (unsigned)pc;
    if (cls >= (unsigned)NCELL) cls = 0;

    float rel = cell_rel[cls] / 100.0f;
    float fac = (rel >= THR_REL) ? 0.01f * rel : 0.0f;
    float4 w = *(const float4*)&W[(size_t)cls * DIM + t * 4];
    float4 e;
    e.x = fac * (w.x - x.x);
    e.y = fac * (w.y - x.y);
    e.z = fac * (w.z - x.z);
    e.w = fac * (w.w - x.w);
    *(float4*)&out_err[(size_t)i * DIM + t * 4] = e;

    int bx = (int)(bmu / GRID), by = (int)(bmu % GRID);
    int center = by * GRID + bx;
    float* dst = &g_S0[(size_t)center * DIM + t * 4];
    atomicAdd(dst + 0, x.x);
    atomicAdd(dst + 1, x.y);
    atomicAdd(dst + 2, x.z);
    atomicAdd(dst + 3, x.w);
    if (t == 0) atomicAdd(&g_cnt[center], 1.0f);
}

// ---------------- stencil conv + SOM update ----------------
__global__ void update_kernel(const float* __restrict__ som,
                              float* __restrict__ out_som) {
    const int cell = blockIdx.x;
    const int a = cell >> 7, c = cell & 127;
    const int t = threadIdx.x;
    const int ctx = g_ctx;
    const float lr = g_lr;
    const bool flag = (g_sum / (float)BATCH) > 1e-4f;

    float denom = 0.0f;
    float4 num = make_float4(0.f, 0.f, 0.f, 0.f);
    for (int dy = -ctx; dy <= ctx; dy++) {
        int aa = a + dy;
        if (aa < 0 || aa >= GRID) continue;
        for (int dx = -ctx; dx <= ctx; dx++) {
            int cc = c + dx;
            if (cc < 0 || cc >= GRID) continue;
            int ch = max(abs(dy), abs(dx));
            float w = ldexpf(lr, -ch);
            int nb = aa * GRID + cc;
            denom += w * g_cnt[nb];
            float4 sv = *(const float4*)&g_S0[(size_t)nb * DIM + t * 4];
            num.x += w * sv.x; num.y += w * sv.y;
            num.z += w * sv.z; num.w += w * sv.w;
        }
    }
    float4 smv = *(const float4*)&som[(size_t)cell * DIM + t * 4];
    float4 o;
    if (flag) {
        o.x = smv.x + num.x - smv.x * denom;
        o.y = smv.y + num.y - smv.y * denom;
        o.z = smv.z + num.z - smv.z * denom;
        o.w = smv.w + num.w - smv.w * denom;
    } else {
        o = smv;
    }
    *(float4*)&out_som[(size_t)cell * DIM + t * 4] = o;
}

// ---------------- launch ----------------
extern "C" void kernel_launch(void* const* d_in, const int* in_sizes, int n_in,
                              void* d_out, int out_size) {
    const float* X          = (const float*)d_in[0];
    const int*   labels     = (const int*)  d_in[1];
    const float* som        = (const float*)d_in[2];
    const int*   cell_lab   = (const int*)  d_in[3];
    const float* cell_rel   = (const float*)d_in[4];
    const int*   epoch      = (const int*)  d_in[5];
    const int*   max_epochs = (const int*)  d_in[6];
    (void)in_sizes; (void)n_in; (void)out_size;

    float* out_err = (float*)d_out;
    float* out_som = (float*)d_out + (size_t)BATCH * DIM;

    cudaFuncSetAttribute(mma_argmin_kernel,
                         cudaFuncAttributeMaxDynamicSharedMemorySize, SMEMT);

    void *pS0, *pCnt, *pSum;
    cudaGetSymbolAddress(&pS0,  g_S0);
    cudaGetSymbolAddress(&pCnt, g_cnt);
    cudaGetSymbolAddress(&pSum, g_sum);
    cudaMemsetAsync(pS0,  0, sizeof(float) * (size_t)NCELL * DIM);
    cudaMemsetAsync(pCnt, 0, sizeof(float) * NCELL);
    cudaMemsetAsync(pSum, 0, sizeof(float));

    void *pxh, *pwh, *pwl;
    cudaGetSymbolAddress(&pxh, g_xh);
    cudaGetSymbolAddress(&pwh, g_wh); cudaGetSymbolAddress(&pwl, g_wl);

    schedule_kernel<<<1, 1>>>(epoch, max_epochs);
    split_hi_kernel<<<1024, 256>>>(X, (__nv_bfloat16*)pxh, BATCH * DIM / 4);
    split_bf16_kernel<<<2048, 256>>>(som, (__nv_bfloat16*)pwh, (__nv_bfloat16*)pwl,
                                     NCELL * DIM / 4);
    wnorm_kernel<<<NCELL / 8, 256>>>(som);
    mma_argmin_kernel<<<dim3(NCELL / 128, BATCH / 128), 256, SMEMT>>>(labels, cell_lab);
    reduce_rescore_kernel<<<BATCH / 8, 256>>>(X, som);
    persample_kernel<<<BATCH, 128>>>(X, som, cell_rel, out_err);
    update_kernel<<<NCELL, 128>>>(som, out_som);
}

// round 6
// speedup vs baseline: 3.4913x; 1.3202x over previous
#include <cuda_runtime.h>
#include <cuda_fp16.h>
#include <cstdint>

#define BATCH 4096
#define DIM   512
#define GRID  128
#define NCELL (GRID*GRID)   // 16384
#define THR_REL 0.95f
#define LR_MAX 0.2f
#define LR_MIN 0.05f
#define CTX_MAX 2
#define CTX_MIN 0

// GEMM tiling: CTA 128x128, 8 warps (2x4), warp 64x32, k-slab 64, 4-stage pipe
#define KC 64
#define NS (DIM/KC)          // 8 slabs
#define APITCH 144           // bytes per smem row (64 fp16 = 128B data + 16B pad)
#define ARR (128*APITCH)     // 18432 bytes per smem array
#define STG (2*ARR)          // A, B = 36864
#define HDR 1536
#define SMEMT (HDR + 4*STG)  // 148992
#define NPART 512            // (NCELL/128 col tiles) * 4 warp-col groups

typedef unsigned long long u64;

// ---------------- device scratch ----------------
__device__ float   g_wnorm[NCELL];
__device__ u64     g_min[BATCH];
__device__ u64     g_cls[BATCH];
__device__ float   g_S0[NCELL * DIM];
__device__ float   g_cnt[NCELL];
__device__ float   g_sum;
__device__ float   g_lr;
__device__ int     g_ctx;
__device__ __half  g_xf[BATCH*DIM];
__device__ __half  g_wf[NCELL*DIM];
__device__ u64     g_part[(size_t)NPART * BATCH * 4];

// ---------------- PTX helpers (baseline ISA only) ----------------
__device__ __forceinline__ uint32_t smem_to_u32(const void* p) {
    uint32_t a;
    asm("{ .reg .u64 t; cvta.to.shared.u64 t, %1; cvt.u32.u64 %0, t; }" : "=r"(a) : "l"(p));
    return a;
}
#define CP_ASYNC16(d, s) \
    asm volatile("cp.async.cg.shared.global [%0], [%1], 16;" :: "r"(d), "l"(s) : "memory")
#define CP_COMMIT() asm volatile("cp.async.commit_group;" ::: "memory")
#define CP_WAIT(n)  asm volatile("cp.async.wait_group %0;" :: "n"(n) : "memory")

#define LDSM_X4(r, a) \
    asm volatile("ldmatrix.sync.aligned.m8n8.x4.shared.b16 {%0,%1,%2,%3}, [%4];" \
        : "=r"((r)[0]), "=r"((r)[1]), "=r"((r)[2]), "=r"((r)[3]) : "r"(a))
#define LDSM_X2(r, a) \
    asm volatile("ldmatrix.sync.aligned.m8n8.x2.shared.b16 {%0,%1}, [%2];" \
        : "=r"((r)[0]), "=r"((r)[1]) : "r"(a))
#define MMA_F16(dd, aa, bb) \
    asm volatile("mma.sync.aligned.m16n8k16.row.col.f32.f16.f16.f32 " \
        "{%0,%1,%2,%3}, {%4,%5,%6,%7}, {%8,%9}, {%0,%1,%2,%3};" \
        : "+f"((dd)[0]), "+f"((dd)[1]), "+f"((dd)[2]), "+f"((dd)[3]) \
        : "r"((aa)[0]), "r"((aa)[1]), "r"((aa)[2]), "r"((aa)[3]), \
          "r"((bb)[0]), "r"((bb)[1]))

__device__ __forceinline__ unsigned float_to_ordered(float f) {
    unsigned u = __float_as_uint(f);
    return (u & 0x80000000u) ? ~u : (u ^ 0x80000000u);
}
__device__ __forceinline__ void top2_ins(u64& m1, u64& m2, u64 v) {
    if (v < m1) { m2 = m1; m1 = v; } else if (v < m2) { m2 = v; }
}

// ---------------- schedule ----------------
__global__ void schedule_kernel(const int* __restrict__ epoch,
                                const int* __restrict__ max_epochs) {
    int e = epoch[0], me = max_epochs[0];
    float progress = (me > 0) ? (float)(me - e) / (float)me : 0.0f;
    progress = fminf(fmaxf(progress, 0.0f), 1.0f);
    float p2 = progress * progress;
    g_ctx = CTX_MIN + (int)(p2 * p2 * (float)(CTX_MAX - CTX_MIN));
    g_lr  = LR_MIN + progress * (LR_MAX - LR_MIN);
}

// ---------------- fp16 convert ----------------
__global__ void tohalf_kernel(const float* __restrict__ src,
                              __half* __restrict__ dst, int n4) {
    int stride = gridDim.x * blockDim.x;
    for (int i = blockIdx.x * blockDim.x + threadIdx.x; i < n4; i += stride) {
        float4 v = ((const float4*)src)[i];
        union { __half h[4]; uint2 u; } H;
        H.h[0] = __float2half_rn(v.x);
        H.h[1] = __float2half_rn(v.y);
        H.h[2] = __float2half_rn(v.z);
        H.h[3] = __float2half_rn(v.w);
        ((uint2*)dst)[i] = H.u;
    }
}

// ---------------- w_norm ----------------
__global__ void wnorm_kernel(const float* __restrict__ W) {
    int warp = (blockIdx.x * blockDim.x + threadIdx.x) >> 5;
    int lane = threadIdx.x & 31;
    if (warp >= NCELL) return;
    const float4* row = (const float4*)(W + (size_t)warp * DIM);
    float s = 0.0f;
    #pragma unroll
    for (int i = 0; i < 4; i++) {
        float4 v = row[lane + 32 * i];
        s += v.x*v.x + v.y*v.y + v.z*v.z + v.w*v.w;
    }
    #pragma unroll
    for (int o = 16; o; o >>= 1) s += __shfl_xor_sync(0xFFFFFFFFu, s, o);
    if (lane == 0) g_wnorm[warp] = s;
}

// ---------------- fp16 mma.sync GEMM (1-term) + fused top-2 argmin ----------------
__global__ __launch_bounds__(256, 1)
void mma_argmin_kernel(const int* __restrict__ labels,
                       const int* __restrict__ cell_labels) {
    extern __shared__ char sm[];
    const uint32_t sbase = smem_to_u32(sm);
    const int tid = threadIdx.x;
    const int lane = tid & 31;
    const int wid = tid >> 5;
    const int rowBase = blockIdx.y * 128;
    const int colBase = blockIdx.x * 128;

    float* wn_s = (float*)sm;
    int*   cl_s = (int*)(sm + 512);
    int*   rl_s = (int*)(sm + 1024);
    if (tid < 128) {
        wn_s[tid] = g_wnorm[colBase + tid];
        cl_s[tid] = cell_labels[colBase + tid];
        rl_s[tid] = labels[rowBase + tid];
    }

    const int m0  = (wid >> 2) * 64;
    const int n0v = (wid & 3) * 32;

    float d[4][4][4];
    #pragma unroll
    for (int mi = 0; mi < 4; mi++)
        #pragma unroll
        for (int nj = 0; nj < 4; nj++)
            #pragma unroll
            for (int e = 0; e < 4; e++) d[mi][nj][e] = 0.0f;

    // lane-address components for ldmatrix
    const uint32_t aR = (uint32_t)(lane & 15);
    const uint32_t aK = (uint32_t)((lane >> 4) * 8);
    const uint32_t bR = (uint32_t)(lane & 7);
    const uint32_t bK = (uint32_t)(((lane >> 3) & 1) * 8);

    // stage loader via cp.async: A, B (8 x 16B per thread)
    auto load_stage = [&](int s) {
        const int k0 = s * KC;
        const uint32_t st = (uint32_t)HDR + (uint32_t)(s & 3) * STG;
        #pragma unroll
        for (int i = 0; i < 4; i++) {
            int slot = tid + i * 256;            // 0..1023
            int r = slot >> 3, q = slot & 7;
            uint32_t doff = sbase + st + (uint32_t)(r * APITCH + q * 16);
            CP_ASYNC16(doff,       &g_xf[(size_t)(rowBase + r) * DIM + k0 + q * 8]);
            CP_ASYNC16(doff + ARR, &g_wf[(size_t)(colBase + r) * DIM + k0 + q * 8]);
        }
    };

    load_stage(0); CP_COMMIT();
    load_stage(1); CP_COMMIT();
    load_stage(2); CP_COMMIT();

    for (int s = 0; s < NS; s++) {
        CP_WAIT(2);
        __syncthreads();
        const uint32_t st = sbase + (uint32_t)HDR + (uint32_t)(s & 3) * STG;
        #pragma unroll
        for (int ks = 0; ks < KC / 16; ks++) {
            uint32_t a[4][4], b[4][2];
            #pragma unroll
            for (int mi = 0; mi < 4; mi++) {
                uint32_t ad = st + (uint32_t)((m0 + mi * 16 + aR) * APITCH) +
                              (uint32_t)((ks * 16 + aK) * 2);
                LDSM_X4(a[mi], ad);
            }
            #pragma unroll
            for (int nj = 0; nj < 4; nj++) {
                uint32_t bd = st + ARR + (uint32_t)((n0v + nj * 8 + bR) * APITCH) +
                              (uint32_t)((ks * 16 + bK) * 2);
                LDSM_X2(b[nj], bd);
            }
            #pragma unroll
            for (int mi = 0; mi < 4; mi++)
                #pragma unroll
                for (int nj = 0; nj < 4; nj++)
                    MMA_F16(d[mi][nj], a[mi], b[nj]);
        }
        if (s + 3 < NS) { load_stage(s + 3); CP_COMMIT(); }
    }

    // ---- fused epilogue: per-row top-2 (plain + class-masked) ----
    const int g  = lane >> 2;
    const int t4 = lane & 3;
    #pragma unroll
    for (int mi = 0; mi < 4; mi++) {
        const int lr0 = m0 + mi * 16 + g;
        const int lr1 = lr0 + 8;
        const int lab0 = rl_s[lr0];
        const int lab1 = rl_s[lr1];
        u64 m1a = ~0ull, m2a = ~0ull, c1a = ~0ull, c2a = ~0ull;
        u64 m1b = ~0ull, m2b = ~0ull, c1b = ~0ull, c2b = ~0ull;
        #pragma unroll
        for (int nj = 0; nj < 4; nj++) {
            #pragma unroll
            for (int e = 0; e < 2; e++) {
                int lc = n0v + nj * 8 + t4 * 2 + e;
                float wn = wn_s[lc];
                int   cl = cl_s[lc];
                unsigned col = (unsigned)(colBase + lc);
                float s0 = fmaf(-2.0f, d[mi][nj][e], wn);
                u64 p0 = ((u64)float_to_ordered(s0) << 32) | col;
                top2_ins(m1a, m2a, p0);
                if (cl == lab0) top2_ins(c1a, c2a, p0);
                float s1 = fmaf(-2.0f, d[mi][nj][2 + e], wn);
                u64 p1 = ((u64)float_to_ordered(s1) << 32) | col;
                top2_ins(m1b, m2b, p1);
                if (cl == lab1) top2_ins(c1b, c2b, p1);
            }
        }
        #pragma unroll
        for (int o = 1; o <= 2; o <<= 1) {
            u64 q1, q2;
            q1 = __shfl_xor_sync(0xFFFFFFFFu, m1a, o); q2 = __shfl_xor_sync(0xFFFFFFFFu, m2a, o);
            top2_ins(m1a, m2a, q1); top2_ins(m1a, m2a, q2);
            q1 = __shfl_xor_sync(0xFFFFFFFFu, c1a, o); q2 = __shfl_xor_sync(0xFFFFFFFFu, c2a, o);
            top2_ins(c1a, c2a, q1); top2_ins(c1a, c2a, q2);
            q1 = __shfl_xor_sync(0xFFFFFFFFu, m1b, o); q2 = __shfl_xor_sync(0xFFFFFFFFu, m2b, o);
            top2_ins(m1b, m2b, q1); top2_ins(m1b, m2b, q2);
            q1 = __shfl_xor_sync(0xFFFFFFFFu, c1b, o); q2 = __shfl_xor_sync(0xFFFFFFFFu, c2b, o);
            top2_ins(c1b, c2b, q1); top2_ins(c1b, c2b, q2);
        }
        if (t4 == 0) {
            const size_t tileIdx = (size_t)(blockIdx.x * 4 + (wid & 3));
            size_t pb = (tileIdx * BATCH + (size_t)(rowBase + lr0)) * 4;
            g_part[pb+0] = m1a; g_part[pb+1] = m2a; g_part[pb+2] = c1a; g_part[pb+3] = c2a;
            pb = (tileIdx * BATCH + (size_t)(rowBase + lr1)) * 4;
            g_part[pb+0] = m1b; g_part[pb+1] = m2b; g_part[pb+2] = c1b; g_part[pb+3] = c2b;
        }
    }
}

// ---------------- merge partials + exact fp32 rescore ----------------
__device__ __forceinline__ float warp_dot(const float* __restrict__ x,
                                          const float* __restrict__ w, int lane) {
    const float4* xv = (const float4*)x + lane * 4;
    const float4* wv = (const float4*)w + lane * 4;
    float acc = 0.0f;
    #pragma unroll
    for (int q = 0; q < 4; q++) {
        float4 a = xv[q], b = wv[q];
        acc = fmaf(a.x, b.x, acc); acc = fmaf(a.y, b.y, acc);
        acc = fmaf(a.z, b.z, acc); acc = fmaf(a.w, b.w, acc);
    }
    #pragma unroll
    for (int o = 16; o; o >>= 1) acc += __shfl_xor_sync(0xFFFFFFFFu, acc, o);
    return acc;
}

__global__ void reduce_rescore_kernel(const float* __restrict__ X,
                                      const float* __restrict__ W) {
    const int lane = threadIdx.x & 31;
    const int row = blockIdx.x * 8 + (threadIdx.x >> 5);

    u64 m1 = ~0ull, m2 = ~0ull, c1 = ~0ull, c2 = ~0ull;
    #pragma unroll
    for (int t = 0; t < NPART / 32; t++) {
        int tile = lane + t * 32;
        const ulonglong2* p = (const ulonglong2*)&g_part[((size_t)tile * BATCH + row) * 4];
        ulonglong2 a = p[0], b = p[1];
        top2_ins(m1, m2, a.x); top2_ins(m1, m2, a.y);
        top2_ins(c1, c2, b.x); top2_ins(c1, c2, b.y);
    }
    #pragma unroll
    for (int o = 16; o; o >>= 1) {
        u64 q1 = __shfl_xor_sync(0xFFFFFFFFu, m1, o);
        u64 q2 = __shfl_xor_sync(0xFFFFFFFFu, m2, o);
        top2_ins(m1, m2, q1); top2_ins(m1, m2, q2);
        q1 = __shfl_xor_sync(0xFFFFFFFFu, c1, o);
        q2 = __shfl_xor_sync(0xFFFFFFFFu, c2, o);
        top2_ins(c1, c2, q1); top2_ins(c1, c2, q2);
    }

    const float* xr = X + (size_t)row * DIM;

    unsigned i1 = (unsigned)m1, i2 = (unsigned)m2;
    float s1 = g_wnorm[i1] - 2.0f * warp_dot(xr, W + (size_t)i1 * DIM, lane);
    float s2 = g_wnorm[i2] - 2.0f * warp_dot(xr, W + (size_t)i2 * DIM, lane);
    unsigned best = i1; float sb = s1;
    if (s2 < sb || (s2 == sb && i2 < best)) { best = i2; sb = s2; }
    if (lane == 0)
        g_min[row] = ((u64)float_to_ordered(sb) << 32) | best;

    u64 outc = ~0ull;
    if (c1 != ~0ull) {
        unsigned j1 = (unsigned)c1;
        float t1 = g_wnorm[j1] - 2.0f * warp_dot(xr, W + (size_t)j1 * DIM, lane);
        unsigned bc = j1; float tb = t1;
        if (c2 != ~0ull) {
            unsigned j2 = (unsigned)c2;
            float t2 = g_wnorm[j2] - 2.0f * warp_dot(xr, W + (size_t)j2 * DIM, lane);
            if (t2 < tb || (t2 == tb && j2 < bc)) { bc = j2; tb = t2; }
        }
        outc = ((u64)float_to_ordered(tb) << 32) | bc;
    }
    if (lane == 0) g_cls[row] = outc;
}

// ---------------- per-sample: som_errors, min_dist sum, BMU scatter ----------------
__global__ void persample_kernel(const float* __restrict__ X,
                                 const float* __restrict__ W,
                                 const float* __restrict__ cell_rel,
                                 float* __restrict__ out_err) {
    const int i = blockIdx.x;
    const int t = threadIdx.x;
    float4 x = *(const float4*)&X[(size_t)i * DIM + t * 4];

    float s = x.x*x.x + x.y*x.y + x.z*x.z + x.w*x.w;
    #pragma unroll
    for (int o = 16; o; o >>= 1) s += __shfl_xor_sync(0xFFFFFFFFu, s, o);
    __shared__ float red[4];
    if ((t & 31) == 0) red[t >> 5] = s;
    __syncthreads();
    float xn = red[0] + red[1] + red[2] + red[3];

    u64 pm = g_min[i];
    u64 pc = g_cls[i];
    unsigned bmu = (unsigned)pm;
    unsigned ub  = (unsigned)(pm >> 32);
    ub = (ub & 0x80000000u) ? (ub ^ 0x80000000u) : ~ub;
    float smin = __uint_as_float(ub);
    if (t == 0) atomicAdd(&g_sum, fmaxf(xn + smin, 0.0f));

    unsigned cls = (unsigned)pc;
    if (cls >= (unsigned)NCELL) cls = 0;

    float rel = cell_rel[cls] / 100.0f;
    float fac = (rel >= THR_REL) ? 0.01f * rel : 0.0f;
    float4 w = *(const float4*)&W[(size_t)cls * DIM + t * 4];
    float4 e;
    e.x = fac * (w.x - x.x);
    e.y = fac * (w.y - x.y);
    e.z = fac * (w.z - x.z);
    e.w = fac * (w.w - x.w);
    *(float4*)&out_err[(size_t)i * DIM + t * 4] = e;

    int bx = (int)(bmu / GRID), by = (int)(bmu % GRID);
    int center = by * GRID + bx;
    float* dst = &g_S0[(size_t)center * DIM + t * 4];
    atomicAdd(dst + 0, x.x);
    atomicAdd(dst + 1, x.y);
    atomicAdd(dst + 2, x.z);
    atomicAdd(dst + 3, x.w);
    if (t == 0) atomicAdd(&g_cnt[center], 1.0f);
}

// ---------------- stencil conv + SOM update ----------------
__global__ void update_kernel(const float* __restrict__ som,
                              float* __restrict__ out_som) {
    const int cell = blockIdx.x;
    const int a = cell >> 7, c = cell & 127;
    const int t = threadIdx.x;
    const int ctx = g_ctx;
    const float lr = g_lr;
    const bool flag = (g_sum / (float)BATCH) > 1e-4f;

    float denom = 0.0f;
    float4 num = make_float4(0.f, 0.f, 0.f, 0.f);
    for (int dy = -ctx; dy <= ctx; dy++) {
        int aa = a + dy;
        if (aa < 0 || aa >= GRID) continue;
        for (int dx = -ctx; dx <= ctx; dx++) {
            int cc = c + dx;
            if (cc < 0 || cc >= GRID) continue;
            int ch = max(abs(dy), abs(dx));
            float w = ldexpf(lr, -ch);
            int nb = aa * GRID + cc;
            denom += w * g_cnt[nb];
            float4 sv = *(const float4*)&g_S0[(size_t)nb * DIM + t * 4];
            num.x += w * sv.x; num.y += w * sv.y;
            num.z += w * sv.z; num.w += w * sv.w;
        }
    }
    float4 smv = *(const float4*)&som[(size_t)cell * DIM + t * 4];
    float4 o;
    if (flag) {
        o.x = smv.x + num.x - smv.x * denom;
        o.y = smv.y + num.y - smv.y * denom;
        o.z = smv.z + num.z - smv.z * denom;
        o.w = smv.w + num.w - smv.w * denom;
    } else {
        o = smv;
    }
    *(float4*)&out_som[(size_t)cell * DIM + t * 4] = o;
}

// ---------------- launch ----------------
extern "C" void kernel_launch(void* const* d_in, const int* in_sizes, int n_in,
                              void* d_out, int out_size) {
    const float* X          = (const float*)d_in[0];
    const int*   labels     = (const int*)  d_in[1];
    const float* som        = (const float*)d_in[2];
    const int*   cell_lab   = (const int*)  d_in[3];
    const float* cell_rel   = (const float*)d_in[4];
    const int*   epoch      = (const int*)  d_in[5];
    const int*   max_epochs = (const int*)  d_in[6];
    (void)in_sizes; (void)n_in; (void)out_size;

    float* out_err = (float*)d_out;
    float* out_som = (float*)d_out + (size_t)BATCH * DIM;

    cudaFuncSetAttribute(mma_argmin_kernel,
                         cudaFuncAttributeMaxDynamicSharedMemorySize, SMEMT);

    void *pS0, *pCnt, *pSum;
    cudaGetSymbolAddress(&pS0,  g_S0);
    cudaGetSymbolAddress(&pCnt, g_cnt);
    cudaGetSymbolAddress(&pSum, g_sum);
    cudaMemsetAsync(pS0,  0, sizeof(float) * (size_t)NCELL * DIM);
    cudaMemsetAsync(pCnt, 0, sizeof(float) * NCELL);
    cudaMemsetAsync(pSum, 0, sizeof(float));

    void *pxf, *pwf;
    cudaGetSymbolAddress(&pxf, g_xf);
    cudaGetSymbolAddress(&pwf, g_wf);

    schedule_kernel<<<1, 1>>>(epoch, max_epochs);
    tohalf_kernel<<<1024, 256>>>(X,   (__half*)pxf, BATCH * DIM / 4);
    tohalf_kernel<<<2048, 256>>>(som, (__half*)pwf, NCELL * DIM / 4);
    wnorm_kernel<<<NCELL / 8, 256>>>(som);
    mma_argmin_kernel<<<dim3(NCELL / 128, BATCH / 128), 256, SMEMT>>>(labels, cell_lab);
    reduce_rescore_kernel<<<BATCH / 8, 256>>>(X, som);
    persample_kernel<<<BATCH, 128>>>(X, som, cell_rel, out_err);
    update_kernel<<<NCELL, 128>>>(som, out_som);
}